// round 12
// baseline (speedup 1.0000x reference)
#include <cuda_runtime.h>
#include <cuda_fp16.h>
#include <cstdint>
#include <math.h>

// y[b,y] = softmax_l(U[y].x[b,l]) weighted sum of (F[y].x[b,l]) + fb[y]
// Fused two-GEMM + max-free online softmax, fp16 on mma.sync.m16n8k16.
// Persistent CTAs (296), continuous 3-stage cp.async ring.
// De-convoy: per-warp kk phase rotation (kk ^ wid&3) + STS spread across kk.

constexpr int Bn = 8, Ln = 2500, Dn = 512, Yn = 8921;
constexpr int TM = 64, TN = 128, KC = 64;
constexpr int NKC = Dn / KC;           // 8
constexpr int YT = (Yn + TM - 1) / TM; // 140
constexpr int YP = YT * TM;            // 8960
constexpr int NLT = (Ln + TN - 1) / TN;// 20
constexpr int LP = NLT * TN;           // 2560
constexpr int NG = NLT * NKC;          // 160 chunks per tile
constexpr int NTILE = YT * Bn;         // 1120
constexpr int NSLOT = 296;
constexpr int OFF_U = 0, OFF_F = 8192, OFF_X = 16384;
constexpr int STAGE = 32768;
constexpr int NST = 3;

__host__ __device__ __forceinline__ int slot_sw(int row, int c) {
    return c ^ (row & 7);
}

__device__ __align__(16) __half g_U[(size_t)YP * Dn];   // pre-scaled by log2(e)
__device__ __align__(16) __half g_F[(size_t)YP * Dn];
__device__ __align__(16) __half g_X[(size_t)Bn * LP * Dn];

__device__ __forceinline__ void cpa16(uint32_t dst, const void* src) {
    asm volatile("cp.async.cg.shared.global [%0], [%1], 16;" :: "r"(dst), "l"(src));
}
__device__ __forceinline__ void cp_commit() {
    asm volatile("cp.async.commit_group;" ::: "memory");
}
template <int N>
__device__ __forceinline__ void cp_wait() {
    asm volatile("cp.async.wait_group %0;" :: "n"(N) : "memory");
}
__device__ __forceinline__ void ldm4(uint32_t& r0, uint32_t& r1, uint32_t& r2, uint32_t& r3, uint32_t a) {
    asm volatile("ldmatrix.sync.aligned.m8n8.x4.shared.b16 {%0,%1,%2,%3}, [%4];"
        : "=r"(r0), "=r"(r1), "=r"(r2), "=r"(r3) : "r"(a));
}
__device__ __forceinline__ float ex2f(float x) {
    float r;
    asm("ex2.approx.f32 %0, %1;" : "=f"(r) : "f"(x));
    return r;
}
#define MMA_F16(d, a, bfr)                                                           \
    asm volatile("mma.sync.aligned.m16n8k16.row.col.f32.f16.f16.f32 "                \
        "{%0,%1,%2,%3},{%4,%5,%6,%7},{%8,%9},{%0,%1,%2,%3};"                         \
        : "+f"((d)[0]), "+f"((d)[1]), "+f"((d)[2]), "+f"((d)[3])                     \
        : "r"((a)[0]), "r"((a)[1]), "r"((a)[2]), "r"((a)[3]), "r"((bfr)[0]), "r"((bfr)[1]))

// ---------------- fused prep ----------------
constexpr size_t UF_ELEMS = (size_t)YP * Dn;
constexpr size_t X_ELEMS  = (size_t)Bn * LP * Dn;
__global__ __launch_bounds__(256) void prep_all(const float* __restrict__ U,
                                                const float* __restrict__ F,
                                                const float* __restrict__ x) {
    const size_t stride = (size_t)gridDim.x * blockDim.x;
    for (size_t idx = (size_t)blockIdx.x * blockDim.x + threadIdx.x;
         idx < UF_ELEMS + X_ELEMS; idx += stride) {
        if (idx < UF_ELEMS) {
            int y = (int)(idx >> 9);
            float u = 0.f, f = 0.f;
            if (y < Yn) { u = U[idx] * 1.4426950408889634f; f = F[idx]; }
            g_U[idx] = __float2half_rn(u);
            g_F[idx] = __float2half_rn(f);
        } else {
            size_t xi = idx - UF_ELEMS;
            size_t bl = xi >> 9;
            int l = (int)(bl % LP);
            int b = (int)(bl / LP);
            int d = (int)(xi & 511);
            float v = 0.f;
            if (l < Ln) v = x[((size_t)b * Ln + l) * Dn + d];
            g_X[xi] = __float2half_rn(v);
        }
    }
}

// ---------------- main fused persistent kernel ----------------
__global__ __launch_bounds__(256, 2)
void attn_main(const float* __restrict__ fb, float* __restrict__ out) {
    extern __shared__ __align__(128) char smem[];
    uint32_t sbase;
    asm("{ .reg .u64 t; cvta.to.shared.u64 t, %1; cvt.u32.u64 %0, t; }" : "=r"(sbase) : "l"(smem));
    float2* red = (float2*)(smem + NST * STAGE);

    const int tid = threadIdx.x;
    const int wid = tid >> 5, lane = tid & 31;
    const int wm = wid >> 2, wn = wid & 3;
    const int wphase = wid & 3;            // kk phase rotation per warp
    const int cta = blockIdx.x;

    const int lr0 = tid >> 3;
    const int lcc = tid & 7;

    // ---- producer state ----
    int p_t = cta, p_rem = 0, p_slot = 0;
    const __half* p_u = g_U + (size_t)(p_t % YT) * TM * Dn;
    const __half* p_f = g_F + (size_t)(p_t % YT) * TM * Dn;
    const __half* p_x = g_X + (size_t)(p_t / YT) * LP * Dn;

    auto p_advance = [&]() {
        p_slot = (p_slot == NST - 1) ? 0 : p_slot + 1;
        if (++p_rem == NG) {
            p_rem = 0;
            p_t += NSLOT;
            if (p_t < NTILE) {
                p_u = g_U + (size_t)(p_t % YT) * TM * Dn;
                p_f = g_F + (size_t)(p_t % YT) * TM * Dn;
                p_x = g_X + (size_t)(p_t / YT) * LP * Dn;
            }
        }
    };

    auto produce_full = [&]() {             // prologue only
        if (p_t < NTILE) {
            const int ci = p_rem & 7, lti = p_rem >> 3;
            const uint32_t sb = sbase + (uint32_t)p_slot * STAGE;
            #pragma unroll
            for (int rr = 0; rr < 2; rr++) {
                const int row = lr0 + rr * 32;
                const uint32_t d = (uint32_t)row * 128 + (uint32_t)(slot_sw(row, lcc) << 4);
                const size_t s = (size_t)row * Dn + (size_t)ci * KC + lcc * 8;
                cpa16(sb + OFF_U + d, p_u + s);
                cpa16(sb + OFF_F + d, p_f + s);
            }
            #pragma unroll
            for (int rr = 0; rr < 4; rr++) {
                const int row = lr0 + rr * 32;
                const uint32_t d = (uint32_t)row * 128 + (uint32_t)(slot_sw(row, lcc) << 4);
                const size_t s = ((size_t)lti * TN + row) * Dn + (size_t)ci * KC + lcc * 8;
                cpa16(sb + OFF_X + d, p_x + s);
            }
            p_advance();
        }
        cp_commit();
    };

    // ---- ldmatrix invariants ----
    const int lg = lane >> 3, lr = lane & 7;
    const int rA0 = wm * 32 + lr + (lg & 1) * 8;
    const int cA = lg >> 1;
    const int rB0 = wn * 32 + lr + (lg >> 1) * 8;
    const int cB = lg & 1;
    uint32_t offA0[2], offB0[2];
    #pragma unroll
    for (int t2 = 0; t2 < 2; t2++) {
        const int ra = rA0 + t2 * 16;
        offA0[t2] = (uint32_t)ra * 128 + (uint32_t)(slot_sw(ra, cA) << 4);
        const int rb = rB0 + t2 * 16;
        offB0[t2] = (uint32_t)rb * 128 + (uint32_t)(slot_sw(rb, cB) << 4);
    }

    const int quad = lane >> 2, tc = lane & 3;

    produce_full();
    produce_full();

    int c_slot = 0;
    for (int t = cta; t < NTILE; t += NSLOT) {
        const int yt = t % YT, b = t / YT;
        float z[4] = {0.f, 0.f, 0.f, 0.f}, nw[4] = {0.f, 0.f, 0.f, 0.f};

        for (int lt = 0; lt < NLT; lt++) {
            float accS[2][4][4], accT[2][4][4];
            #pragma unroll
            for (int mt = 0; mt < 2; mt++)
                #pragma unroll
                for (int nt = 0; nt < 4; nt++)
                    #pragma unroll
                    for (int j = 0; j < 4; j++) { accS[mt][nt][j] = 0.f; accT[mt][nt][j] = 0.f; }

            for (int c = 0; c < NKC; c++) {
                cp_wait<1>();
                __syncthreads();

                // snapshot producer chunk (parts issued inside kk loop)
                const bool pv = (p_t < NTILE);
                const int pci = p_rem & 7, plt = p_rem >> 3;
                const uint32_t psb = sbase + (uint32_t)p_slot * STAGE;
                const size_t koff = (size_t)pci * KC + lcc * 8;

                const uint32_t sb = sbase + (uint32_t)c_slot * STAGE;
                c_slot = (c_slot == NST - 1) ? 0 : c_slot + 1;

                #pragma unroll
                for (int kk = 0; kk < 4; kk++) {
                    const uint32_t kx = (uint32_t)((kk ^ wphase) << 5);
                    uint32_t X[4][2], A0[2][4], A1[2][4];
                    #pragma unroll
                    for (int bt = 0; bt < 2; bt++)
                        ldm4(X[bt*2][0], X[bt*2][1], X[bt*2+1][0], X[bt*2+1][1],
                             sb + OFF_X + (offB0[bt] ^ kx));
                    #pragma unroll
                    for (int mt = 0; mt < 2; mt++) {
                        ldm4(A0[mt][0], A0[mt][1], A0[mt][2], A0[mt][3],
                             sb + OFF_U + (offA0[mt] ^ kx));
                        ldm4(A1[mt][0], A1[mt][1], A1[mt][2], A1[mt][3],
                             sb + OFF_F + (offA0[mt] ^ kx));
                    }

                    // producer part kk: 2 cp.asyncs, spread across the chunk
                    if (pv) {
                        if (kk < 2) {
                            #pragma unroll
                            for (int rr = 0; rr < 2; rr++) {
                                const int row = lr0 + rr * 32;
                                const uint32_t d = (uint32_t)row * 128 + (uint32_t)(slot_sw(row, lcc) << 4);
                                const size_t s = (size_t)row * Dn + koff;
                                if (kk == 0) cpa16(psb + OFF_U + d, p_u + s);
                                else         cpa16(psb + OFF_F + d, p_f + s);
                            }
                        } else {
                            #pragma unroll
                            for (int rr = 0; rr < 2; rr++) {
                                const int row = lr0 + (rr + (kk - 2) * 2) * 32;
                                const uint32_t d = (uint32_t)row * 128 + (uint32_t)(slot_sw(row, lcc) << 4);
                                const size_t s = ((size_t)plt * TN + row) * Dn + koff;
                                cpa16(psb + OFF_X + d, p_x + s);
                            }
                        }
                    }

                    #pragma unroll
                    for (int mt = 0; mt < 2; mt++)
                        #pragma unroll
                        for (int nt = 0; nt < 4; nt++) {
                            MMA_F16(accS[mt][nt], A0[mt], X[nt]);
                            MMA_F16(accT[mt][nt], A1[mt], X[nt]);
                        }
                }
                cp_commit();
                if (pv) p_advance();
            }

            // max-free softmax partial update (log2-domain scores, ex2)
            #pragma unroll
            for (int nt = 0; nt < 4; nt++)
                #pragma unroll
                for (int j = 0; j < 4; j++) {
                    const int l = lt * TN + wn * 32 + nt * 8 + tc * 2 + (j & 1);
                    const bool v = (l < Ln);
                    #pragma unroll
                    for (int mt = 0; mt < 2; mt++) {
                        const int zi = mt * 2 + (j >> 1);
                        const float e = v ? ex2f(accS[mt][nt][j]) : 0.f;
                        z[zi] += e;
                        nw[zi] = fmaf(e, accT[mt][nt][j], nw[zi]);
                    }
                }
        }

        // ---- per-tile output ----
        #pragma unroll
        for (int zi = 0; zi < 4; zi++) {
            z[zi]  += __shfl_xor_sync(0xffffffffu, z[zi], 1);
            z[zi]  += __shfl_xor_sync(0xffffffffu, z[zi], 2);
            nw[zi] += __shfl_xor_sync(0xffffffffu, nw[zi], 1);
            nw[zi] += __shfl_xor_sync(0xffffffffu, nw[zi], 2);
        }
        if (tc == 0) {
            #pragma unroll
            for (int zi = 0; zi < 4; zi++) {
                const int mt = zi >> 1, rh = zi & 1;
                const int row = wm * 32 + mt * 16 + rh * 8 + quad;
                red[wn * 64 + row] = make_float2(z[zi], nw[zi]);
            }
        }
        __syncthreads();
        if (tid < 64) {
            float zz = 0.f, nn = 0.f;
            #pragma unroll
            for (int w = 0; w < 4; w++) { float2 v = red[w * 64 + tid]; zz += v.x; nn += v.y; }
            const int y = yt * TM + tid;
            if (y < Yn) out[(size_t)b * Yn + y] = nn / zz + fb[y];
        }
        __syncthreads();
    }
    cp_wait<0>();
}

// ---------------- host launch ----------------
extern "C" void kernel_launch(void* const* d_in, const int* in_sizes, int n_in,
                              void* d_out, int out_size) {
    const float* x  = (const float*)d_in[0];
    const float* Uw = (const float*)d_in[1];
    const float* Fw = (const float*)d_in[2];
    const float* fb = (const float*)d_in[3];
    float* out = (float*)d_out;
    (void)in_sizes; (void)n_in; (void)out_size;

    prep_all<<<4096, 256>>>(Uw, Fw, x);

    const int dyn = NST * STAGE + 2048;
    cudaFuncSetAttribute(attn_main, cudaFuncAttributeMaxDynamicSharedMemorySize, dyn);
    attn_main<<<NSLOT, 256, dyn>>>(fb, out);
}

// round 13
// speedup vs baseline: 1.0846x; 1.0846x over previous
#include <cuda_runtime.h>
#include <cuda_fp16.h>
#include <cstdint>
#include <math.h>

// y[b,y] = softmax_l(U[y].x[b,l]) weighted sum of (F[y].x[b,l]) + fb[y]
// Fused two-GEMM + max-free online softmax, fp16 on mma.sync.m16n8k16.
// 128-thread CTAs (warp grid 2x2, warp tile 32x64) at 2 CTAs/SM:
//  - bytes/MMA 192 -> 128 (crossbar sub-critical vs tensor floor)
//  - 2 warps/SMSP from INDEPENDENT CTAs (barrier/epilogue latency hidden)

constexpr int Bn = 8, Ln = 2500, Dn = 512, Yn = 8921;
constexpr int TM = 64, TN = 128, KC = 64;
constexpr int NKC = Dn / KC;           // 8
constexpr int YT = (Yn + TM - 1) / TM; // 140
constexpr int YP = YT * TM;            // 8960
constexpr int NLT = (Ln + TN - 1) / TN;// 20
constexpr int LP = NLT * TN;           // 2560
constexpr int NG = NLT * NKC;          // 160 chunks per tile
constexpr int OFF_U = 0, OFF_F = 8192, OFF_X = 16384;
constexpr int STAGE = 32768;
constexpr int NST = 3;                 // 96KB/CTA -> 2 CTAs/SM (192KB)

__host__ __device__ __forceinline__ int slot_sw(int row, int c) {
    return c ^ (row & 7);
}

__device__ __align__(16) __half g_U[(size_t)YP * Dn];   // pre-scaled by log2(e)
__device__ __align__(16) __half g_F[(size_t)YP * Dn];
__device__ __align__(16) __half g_X[(size_t)Bn * LP * Dn];

__device__ __forceinline__ void cpa16(uint32_t dst, const void* src) {
    asm volatile("cp.async.cg.shared.global [%0], [%1], 16;" :: "r"(dst), "l"(src));
}
__device__ __forceinline__ void cp_commit() {
    asm volatile("cp.async.commit_group;" ::: "memory");
}
template <int N>
__device__ __forceinline__ void cp_wait() {
    asm volatile("cp.async.wait_group %0;" :: "n"(N) : "memory");
}
__device__ __forceinline__ void ldm4(uint32_t& r0, uint32_t& r1, uint32_t& r2, uint32_t& r3, uint32_t a) {
    asm volatile("ldmatrix.sync.aligned.m8n8.x4.shared.b16 {%0,%1,%2,%3}, [%4];"
        : "=r"(r0), "=r"(r1), "=r"(r2), "=r"(r3) : "r"(a));
}
__device__ __forceinline__ float ex2f(float x) {
    float r;
    asm("ex2.approx.f32 %0, %1;" : "=f"(r) : "f"(x));
    return r;
}
#define MMA_F16(d, a, bfr)                                                           \
    asm volatile("mma.sync.aligned.m16n8k16.row.col.f32.f16.f16.f32 "                \
        "{%0,%1,%2,%3},{%4,%5,%6,%7},{%8,%9},{%0,%1,%2,%3};"                         \
        : "+f"((d)[0]), "+f"((d)[1]), "+f"((d)[2]), "+f"((d)[3])                     \
        : "r"((a)[0]), "r"((a)[1]), "r"((a)[2]), "r"((a)[3]), "r"((bfr)[0]), "r"((bfr)[1]))

// ---------------- fused prep: fp32 -> fp16 (U scaled by log2 e) ----------------
constexpr size_t UF_ELEMS = (size_t)YP * Dn;
constexpr size_t X_ELEMS  = (size_t)Bn * LP * Dn;
__global__ __launch_bounds__(256) void prep_all(const float* __restrict__ U,
                                                const float* __restrict__ F,
                                                const float* __restrict__ x) {
    const size_t stride = (size_t)gridDim.x * blockDim.x;
    for (size_t idx = (size_t)blockIdx.x * blockDim.x + threadIdx.x;
         idx < UF_ELEMS + X_ELEMS; idx += stride) {
        if (idx < UF_ELEMS) {
            int y = (int)(idx >> 9);
            float u = 0.f, f = 0.f;
            if (y < Yn) { u = U[idx] * 1.4426950408889634f; f = F[idx]; }
            g_U[idx] = __float2half_rn(u);
            g_F[idx] = __float2half_rn(f);
        } else {
            size_t xi = idx - UF_ELEMS;
            size_t bl = xi >> 9;
            int l = (int)(bl % LP);
            int b = (int)(bl / LP);
            int d = (int)(xi & 511);
            float v = 0.f;
            if (l < Ln) v = x[((size_t)b * Ln + l) * Dn + d];
            g_X[xi] = __float2half_rn(v);
        }
    }
}

// ---------------- main fused kernel: 128 threads, 4 warps ----------------
__global__ __launch_bounds__(128, 2)
void attn_main(const float* __restrict__ fb, float* __restrict__ out) {
    extern __shared__ __align__(128) char smem[];
    uint32_t sbase;
    asm("{ .reg .u64 t; cvta.to.shared.u64 t, %1; cvt.u32.u64 %0, t; }" : "=r"(sbase) : "l"(smem));
    float2* red = (float2*)(smem + NST * STAGE);   // [2 wn][64 rows] = 1KB

    const int tid = threadIdx.x;
    const int wid = tid >> 5, lane = tid & 31;
    const int wm = wid >> 1, wn = wid & 1;        // warp grid 2(M) x 2(N); warp tile 32x64
    const int yt = blockIdx.x, b = blockIdx.y;

    // ---- loader mapping: 8 threads per 128B row; 16 rows per pass ----
    const int lr0 = tid >> 3;                     // 0..15
    const int lcc = tid & 7;                      // 16B chunk in 128B row

    auto issue = [&](int gi) {
        const int ci = gi & 7, lti = gi >> 3;
        const uint32_t sb = sbase + (uint32_t)(gi % NST) * STAGE;
        #pragma unroll
        for (int rr = 0; rr < 4; rr++) {
            const int row = lr0 + rr * 16;
            const uint32_t d = (uint32_t)row * 128 + (uint32_t)(slot_sw(row, lcc) << 4);
            const size_t s = ((size_t)(yt * TM + row)) * Dn + (size_t)ci * KC + lcc * 8;
            cpa16(sb + OFF_U + d, g_U + s);
            cpa16(sb + OFF_F + d, g_F + s);
        }
        #pragma unroll
        for (int rr = 0; rr < 8; rr++) {
            const int row = lr0 + rr * 16;
            const uint32_t d = (uint32_t)row * 128 + (uint32_t)(slot_sw(row, lcc) << 4);
            const size_t s = ((size_t)b * LP + (size_t)lti * TN + row) * Dn + (size_t)ci * KC + lcc * 8;
            cpa16(sb + OFF_X + d, g_X + s);
        }
    };

    // ---- ldmatrix per-thread invariants ----
    const int lg = lane >> 3, lr = lane & 7;
    const int rA0 = wm * 32 + lr + (lg & 1) * 8;        // A: grp bit0 = row half, bit1 = k half
    const int cA = lg >> 1;
    const int rB0 = wn * 64 + lr + (lg >> 1) * 8;       // B: grp bit1 = n half, bit0 = k half
    const int cB = lg & 1;
    // base offsets (kk=0); off[kk] = off0 ^ (kk<<5)
    uint32_t offA0[2], offB0[4];
    #pragma unroll
    for (int t2 = 0; t2 < 2; t2++) {
        const int ra = rA0 + t2 * 16;
        offA0[t2] = (uint32_t)ra * 128 + (uint32_t)(slot_sw(ra, cA) << 4);
    }
    #pragma unroll
    for (int bt = 0; bt < 4; bt++) {
        const int rb = rB0 + bt * 16;
        offB0[bt] = (uint32_t)rb * 128 + (uint32_t)(slot_sw(rb, cB) << 4);
    }

    const int quad = lane >> 2, tc = lane & 3;

    float z[4] = {0.f, 0.f, 0.f, 0.f}, nw[4] = {0.f, 0.f, 0.f, 0.f};

    // prologue: 2 stages in flight (3-buffer ring)
    issue(0); cp_commit();
    issue(1); cp_commit();

    for (int lt = 0; lt < NLT; lt++) {
        float accS[2][8][4], accT[2][8][4];
        #pragma unroll
        for (int mt = 0; mt < 2; mt++)
            #pragma unroll
            for (int nt = 0; nt < 8; nt++)
                #pragma unroll
                for (int j = 0; j < 4; j++) { accS[mt][nt][j] = 0.f; accT[mt][nt][j] = 0.f; }

        for (int c = 0; c < NKC; c++) {
            const int g = lt * NKC + c;
            cp_wait<1>();
            __syncthreads();
            const int gi = g + 2;
            if (gi < NG) issue(gi);
            cp_commit();

            const uint32_t sb = sbase + (uint32_t)(g % NST) * STAGE;
            #pragma unroll
            for (int kk = 0; kk < 4; kk++) {
                const uint32_t kx = (uint32_t)(kk << 5);
                uint32_t X[8][2], A0[2][4], A1[2][4];
                #pragma unroll
                for (int bt = 0; bt < 4; bt++)
                    ldm4(X[bt*2][0], X[bt*2][1], X[bt*2+1][0], X[bt*2+1][1],
                         sb + OFF_X + (offB0[bt] ^ kx));
                #pragma unroll
                for (int mt = 0; mt < 2; mt++) {
                    ldm4(A0[mt][0], A0[mt][1], A0[mt][2], A0[mt][3], sb + OFF_U + (offA0[mt] ^ kx));
                    ldm4(A1[mt][0], A1[mt][1], A1[mt][2], A1[mt][3], sb + OFF_F + (offA0[mt] ^ kx));
                }
                #pragma unroll
                for (int mt = 0; mt < 2; mt++)
                    #pragma unroll
                    for (int nt = 0; nt < 8; nt++) {
                        MMA_F16(accS[mt][nt], A0[mt], X[nt]);
                        MMA_F16(accT[mt][nt], A1[mt], X[nt]);
                    }
            }
        }

        // max-free softmax partial update (log2-domain scores, ex2)
        #pragma unroll
        for (int nt = 0; nt < 8; nt++)
            #pragma unroll
            for (int j = 0; j < 4; j++) {
                const int l = lt * TN + wn * 64 + nt * 8 + tc * 2 + (j & 1);
                const bool v = (l < Ln);
                #pragma unroll
                for (int mt = 0; mt < 2; mt++) {
                    const int zi = mt * 2 + (j >> 1);
                    const float e = v ? ex2f(accS[mt][nt][j]) : 0.f;
                    z[zi] += e;
                    nw[zi] = fmaf(e, accT[mt][nt][j], nw[zi]);
                }
            }
    }

    // ---- final reduction ----
    cp_wait<0>();
    __syncthreads();
    #pragma unroll
    for (int zi = 0; zi < 4; zi++) {
        z[zi]  += __shfl_xor_sync(0xffffffffu, z[zi], 1);
        z[zi]  += __shfl_xor_sync(0xffffffffu, z[zi], 2);
        nw[zi] += __shfl_xor_sync(0xffffffffu, nw[zi], 1);
        nw[zi] += __shfl_xor_sync(0xffffffffu, nw[zi], 2);
    }
    if (tc == 0) {
        #pragma unroll
        for (int zi = 0; zi < 4; zi++) {
            const int mt = zi >> 1, rh = zi & 1;
            const int row = wm * 32 + mt * 16 + rh * 8 + quad;
            red[wn * 64 + row] = make_float2(z[zi], nw[zi]);
        }
    }
    __syncthreads();
    if (tid < 64) {
        float zz = 0.f, nn = 0.f;
        #pragma unroll
        for (int w = 0; w < 2; w++) { float2 v = red[w * 64 + tid]; zz += v.x; nn += v.y; }
        const int y = yt * TM + tid;
        if (y < Yn) out[(size_t)b * Yn + y] = nn / zz + fb[y];
    }
}

// ---------------- host launch ----------------
extern "C" void kernel_launch(void* const* d_in, const int* in_sizes, int n_in,
                              void* d_out, int out_size) {
    const float* x  = (const float*)d_in[0];
    const float* Uw = (const float*)d_in[1];
    const float* Fw = (const float*)d_in[2];
    const float* fb = (const float*)d_in[3];
    float* out = (float*)d_out;
    (void)in_sizes; (void)n_in; (void)out_size;

    prep_all<<<4096, 256>>>(Uw, Fw, x);

    const int dyn = NST * STAGE + 1024;
    cudaFuncSetAttribute(attn_main, cudaFuncAttributeMaxDynamicSharedMemorySize, dyn);
    attn_main<<<dim3(YT, Bn), 128, dyn>>>(fb, out);
}

// round 16
// speedup vs baseline: 1.1001x; 1.0142x over previous
#include <cuda_runtime.h>
#include <cuda_fp16.h>
#include <cstdint>
#include <math.h>

// y[b,y] = softmax_l(U[y].x[b,l]) weighted sum of (F[y].x[b,l]) + fb[y]
// Fused two-GEMM + max-free online softmax, fp16 on mma.sync.m16n8k16.
// 128-thread CTAs (warp grid 2x2, warp tile 32x64), 2 CTAs/SM, 3-stage ring.
// S-GEMM uses f16 ACCUMULATORS (6-reg HMMA form); scores emerge f16x2-packed
// -> h2exp2 epilogue (intrinsics only; no hand PTX in the epilogue).

constexpr int Bn = 8, Ln = 2500, Dn = 512, Yn = 8921;
constexpr int TM = 64, TN = 128, KC = 64;
constexpr int NKC = Dn / KC;           // 8
constexpr int YT = (Yn + TM - 1) / TM; // 140
constexpr int YP = YT * TM;            // 8960
constexpr int NLT = (Ln + TN - 1) / TN;// 20
constexpr int LP = NLT * TN;           // 2560
constexpr int NG = NLT * NKC;          // 160 chunks per tile
constexpr int OFF_U = 0, OFF_F = 8192, OFF_X = 16384;
constexpr int STAGE = 32768;
constexpr int NST = 3;                 // 96KB/CTA -> 2 CTAs/SM

__host__ __device__ __forceinline__ int slot_sw(int row, int c) {
    return c ^ (row & 7);
}

__device__ __align__(16) __half g_U[(size_t)YP * Dn];   // pre-scaled by log2(e)
__device__ __align__(16) __half g_F[(size_t)YP * Dn];
__device__ __align__(16) __half g_X[(size_t)Bn * LP * Dn];

__device__ __forceinline__ void cpa16(uint32_t dst, const void* src) {
    asm volatile("cp.async.cg.shared.global [%0], [%1], 16;" :: "r"(dst), "l"(src));
}
__device__ __forceinline__ void cp_commit() {
    asm volatile("cp.async.commit_group;" ::: "memory");
}
template <int N>
__device__ __forceinline__ void cp_wait() {
    asm volatile("cp.async.wait_group %0;" :: "n"(N) : "memory");
}
__device__ __forceinline__ void ldm4(uint32_t& r0, uint32_t& r1, uint32_t& r2, uint32_t& r3, uint32_t a) {
    asm volatile("ldmatrix.sync.aligned.m8n8.x4.shared.b16 {%0,%1,%2,%3}, [%4];"
        : "=r"(r0), "=r"(r1), "=r"(r2), "=r"(r3) : "r"(a));
}
// S: f16 accumulators (2 regs)
#define MMA_F16H(d, a, bfr)                                                          \
    asm volatile("mma.sync.aligned.m16n8k16.row.col.f16.f16.f16.f16 "                \
        "{%0,%1},{%2,%3,%4,%5},{%6,%7},{%0,%1};"                                     \
        : "+r"((d)[0]), "+r"((d)[1])                                                 \
        : "r"((a)[0]), "r"((a)[1]), "r"((a)[2]), "r"((a)[3]), "r"((bfr)[0]), "r"((bfr)[1]))
// T: f32 accumulators (4 regs)
#define MMA_F16(d, a, bfr)                                                           \
    asm volatile("mma.sync.aligned.m16n8k16.row.col.f32.f16.f16.f32 "                \
        "{%0,%1,%2,%3},{%4,%5,%6,%7},{%8,%9},{%0,%1,%2,%3};"                         \
        : "+f"((d)[0]), "+f"((d)[1]), "+f"((d)[2]), "+f"((d)[3])                     \
        : "r"((a)[0]), "r"((a)[1]), "r"((a)[2]), "r"((a)[3]), "r"((bfr)[0]), "r"((bfr)[1]))

// ---------------- fused prep: fp32 -> fp16 (U scaled by log2 e) ----------------
constexpr size_t UF_ELEMS = (size_t)YP * Dn;
constexpr size_t X_ELEMS  = (size_t)Bn * LP * Dn;
__global__ __launch_bounds__(256) void prep_all(const float* __restrict__ U,
                                                const float* __restrict__ F,
                                                const float* __restrict__ x) {
    const size_t stride = (size_t)gridDim.x * blockDim.x;
    for (size_t idx = (size_t)blockIdx.x * blockDim.x + threadIdx.x;
         idx < UF_ELEMS + X_ELEMS; idx += stride) {
        if (idx < UF_ELEMS) {
            int y = (int)(idx >> 9);
            float u = 0.f, f = 0.f;
            if (y < Yn) { u = U[idx] * 1.4426950408889634f; f = F[idx]; }
            g_U[idx] = __float2half_rn(u);
            g_F[idx] = __float2half_rn(f);
        } else {
            size_t xi = idx - UF_ELEMS;
            size_t bl = xi >> 9;
            int l = (int)(bl % LP);
            int b = (int)(bl / LP);
            int d = (int)(xi & 511);
            float v = 0.f;
            if (l < Ln) v = x[((size_t)b * Ln + l) * Dn + d];
            g_X[xi] = __float2half_rn(v);
        }
    }
}

// ---------------- main fused kernel: 128 threads, 4 warps ----------------
__global__ __launch_bounds__(128, 2)
void attn_main(const float* __restrict__ fb, float* __restrict__ out) {
    extern __shared__ __align__(128) char smem[];
    uint32_t sbase;
    asm("{ .reg .u64 t; cvta.to.shared.u64 t, %1; cvt.u32.u64 %0, t; }" : "=r"(sbase) : "l"(smem));
    float2* red = (float2*)(smem + NST * STAGE);   // [2 wn][64 rows] = 1KB

    const int tid = threadIdx.x;
    const int wid = tid >> 5, lane = tid & 31;
    const int wm = wid >> 1, wn = wid & 1;        // warp grid 2(M) x 2(N); warp tile 32x64
    const int yt = blockIdx.x, b = blockIdx.y;

    // ---- loader mapping: 8 threads per 128B row; 16 rows per pass ----
    const int lr0 = tid >> 3;                     // 0..15
    const int lcc = tid & 7;                      // 16B chunk in 128B row

    auto issue = [&](int gi) {
        const int ci = gi & 7, lti = gi >> 3;
        const uint32_t sb = sbase + (uint32_t)(gi % NST) * STAGE;
        #pragma unroll
        for (int rr = 0; rr < 4; rr++) {
            const int row = lr0 + rr * 16;
            const uint32_t d = (uint32_t)row * 128 + (uint32_t)(slot_sw(row, lcc) << 4);
            const size_t s = ((size_t)(yt * TM + row)) * Dn + (size_t)ci * KC + lcc * 8;
            cpa16(sb + OFF_U + d, g_U + s);
            cpa16(sb + OFF_F + d, g_F + s);
        }
        #pragma unroll
        for (int rr = 0; rr < 8; rr++) {
            const int row = lr0 + rr * 16;
            const uint32_t d = (uint32_t)row * 128 + (uint32_t)(slot_sw(row, lcc) << 4);
            const size_t s = ((size_t)b * LP + (size_t)lti * TN + row) * Dn + (size_t)ci * KC + lcc * 8;
            cpa16(sb + OFF_X + d, g_X + s);
        }
    };

    // ---- ldmatrix per-thread invariants ----
    const int lg = lane >> 3, lr = lane & 7;
    const int rA0 = wm * 32 + lr + (lg & 1) * 8;
    const int cA = lg >> 1;
    const int rB0 = wn * 64 + lr + (lg >> 1) * 8;
    const int cB = lg & 1;
    uint32_t offA0[2], offB0[4];
    #pragma unroll
    for (int t2 = 0; t2 < 2; t2++) {
        const int ra = rA0 + t2 * 16;
        offA0[t2] = (uint32_t)ra * 128 + (uint32_t)(slot_sw(ra, cA) << 4);
    }
    #pragma unroll
    for (int bt = 0; bt < 4; bt++) {
        const int rb = rB0 + bt * 16;
        offB0[bt] = (uint32_t)rb * 128 + (uint32_t)(slot_sw(rb, cB) << 4);
    }

    const int quad = lane >> 2, tc = lane & 3;

    float z[4] = {0.f, 0.f, 0.f, 0.f}, nw[4] = {0.f, 0.f, 0.f, 0.f};

    issue(0); cp_commit();
    issue(1); cp_commit();

    for (int lt = 0; lt < NLT; lt++) {
        __half2 accS[2][8][2];                    // f16x2 accumulators for S
        float accT[2][8][4];
        #pragma unroll
        for (int mt = 0; mt < 2; mt++)
            #pragma unroll
            for (int nt = 0; nt < 8; nt++) {
                accS[mt][nt][0] = __half2half2(__ushort_as_half(0));
                accS[mt][nt][1] = __half2half2(__ushort_as_half(0));
                #pragma unroll
                for (int j = 0; j < 4; j++) accT[mt][nt][j] = 0.f;
            }

        for (int c = 0; c < NKC; c++) {
            const int g = lt * NKC + c;
            cp_wait<1>();
            __syncthreads();
            const int gi = g + 2;
            if (gi < NG) issue(gi);
            cp_commit();

            const uint32_t sb = sbase + (uint32_t)(g % NST) * STAGE;
            #pragma unroll
            for (int kk = 0; kk < 4; kk++) {
                const uint32_t kx = (uint32_t)(kk << 5);
                uint32_t X[8][2], A0[2][4], A1[2][4];
                #pragma unroll
                for (int bt = 0; bt < 4; bt++)
                    ldm4(X[bt*2][0], X[bt*2][1], X[bt*2+1][0], X[bt*2+1][1],
                         sb + OFF_X + (offB0[bt] ^ kx));
                #pragma unroll
                for (int mt = 0; mt < 2; mt++) {
                    ldm4(A0[mt][0], A0[mt][1], A0[mt][2], A0[mt][3], sb + OFF_U + (offA0[mt] ^ kx));
                    ldm4(A1[mt][0], A1[mt][1], A1[mt][2], A1[mt][3], sb + OFF_F + (offA0[mt] ^ kx));
                }
                #pragma unroll
                for (int mt = 0; mt < 2; mt++)
                    #pragma unroll
                    for (int nt = 0; nt < 8; nt++) {
                        uint32_t* sAcc = reinterpret_cast<uint32_t*>(accS[mt][nt]);
                        MMA_F16H(sAcc, A0[mt], X[nt]);
                        MMA_F16(accT[mt][nt], A1[mt], X[nt]);
                    }
            }
        }

        // softmax partial update: h2exp2 on packed scores, masked f32 accumulate
        #pragma unroll
        for (int nt = 0; nt < 8; nt++) {
            const int l0 = lt * TN + wn * 64 + nt * 8 + tc * 2;  // even; pair (l0, l0+1)
            const bool v = (l0 < Ln);                            // Ln even -> pair-uniform
            #pragma unroll
            for (int mt = 0; mt < 2; mt++)
                #pragma unroll
                for (int h = 0; h < 2; h++) {                    // row quad / quad+8
                    const __half2 e2 = h2exp2(accS[mt][nt][h]);
                    const float eA = __low2float(e2);
                    const float eB = __high2float(e2);
                    if (v) {
                        const int zi = mt * 2 + h;
                        z[zi] += eA + eB;
                        nw[zi] = fmaf(eA, accT[mt][nt][h * 2],     nw[zi]);
                        nw[zi] = fmaf(eB, accT[mt][nt][h * 2 + 1], nw[zi]);
                    }
                }
        }
    }

    // ---- final reduction ----
    cp_wait<0>();
    __syncthreads();
    #pragma unroll
    for (int zi = 0; zi < 4; zi++) {
        z[zi]  += __shfl_xor_sync(0xffffffffu, z[zi], 1);
        z[zi]  += __shfl_xor_sync(0xffffffffu, z[zi], 2);
        nw[zi] += __shfl_xor_sync(0xffffffffu, nw[zi], 1);
        nw[zi] += __shfl_xor_sync(0xffffffffu, nw[zi], 2);
    }
    if (tc == 0) {
        #pragma unroll
        for (int zi = 0; zi < 4; zi++) {
            const int mt = zi >> 1, rh = zi & 1;
            const int row = wm * 32 + mt * 16 + rh * 8 + quad;
            red[wn * 64 + row] = make_float2(z[zi], nw[zi]);
        }
    }
    __syncthreads();
    if (tid < 64) {
        float zz = 0.f, nn = 0.f;
        #pragma unroll
        for (int w = 0; w < 2; w++) { float2 v = red[w * 64 + tid]; zz += v.x; nn += v.y; }
        const int y = yt * TM + tid;
        if (y < Yn) out[(size_t)b * Yn + y] = nn / zz + fb[y];
    }
}

// ---------------- host launch ----------------
extern "C" void kernel_launch(void* const* d_in, const int* in_sizes, int n_in,
                              void* d_out, int out_size) {
    const float* x  = (const float*)d_in[0];
    const float* Uw = (const float*)d_in[1];
    const float* Fw = (const float*)d_in[2];
    const float* fb = (const float*)d_in[3];
    float* out = (float*)d_out;
    (void)in_sizes; (void)n_in; (void)out_size;

    prep_all<<<4096, 256>>>(Uw, Fw, x);

    const int dyn = NST * STAGE + 1024;
    cudaFuncSetAttribute(attn_main, cudaFuncAttributeMaxDynamicSharedMemorySize, dyn);
    attn_main<<<dim3(YT, Bn), 128, dyn>>>(fb, out);
}

// round 17
// speedup vs baseline: 1.1767x; 1.0697x over previous
#include <cuda_runtime.h>
#include <cuda_fp16.h>
#include <cstdint>
#include <math.h>

// y[b,y] = softmax_l(U[y].x[b,l]) weighted sum of (F[y].x[b,l]) + fb[y]
// Fused two-GEMM + max-free online softmax, fp16 on mma.sync.m16n8k16.
// 128-thread CTAs (warp grid 2x2, warp tile 32x64), 2 CTAs/SM, 3-stage ring.
// S-GEMM: f16 accumulators; h2exp2 epilogue. Vectorized prep (float4 -> half2x2).
// kk=0 fragments hoisted ahead of the cp.async burst at each chunk entry.

constexpr int Bn = 8, Ln = 2500, Dn = 512, Yn = 8921;
constexpr int TM = 64, TN = 128, KC = 64;
constexpr int NKC = Dn / KC;           // 8
constexpr int YT = (Yn + TM - 1) / TM; // 140
constexpr int YP = YT * TM;            // 8960
constexpr int NLT = (Ln + TN - 1) / TN;// 20
constexpr int LP = NLT * TN;           // 2560
constexpr int NG = NLT * NKC;          // 160 chunks per tile
constexpr int OFF_U = 0, OFF_F = 8192, OFF_X = 16384;
constexpr int STAGE = 32768;
constexpr int NST = 3;                 // 96KB/CTA -> 2 CTAs/SM

__host__ __device__ __forceinline__ int slot_sw(int row, int c) {
    return c ^ (row & 7);
}

__device__ __align__(16) __half g_U[(size_t)YP * Dn];   // pre-scaled by log2(e)
__device__ __align__(16) __half g_F[(size_t)YP * Dn];
__device__ __align__(16) __half g_X[(size_t)Bn * LP * Dn];

__device__ __forceinline__ void cpa16(uint32_t dst, const void* src) {
    asm volatile("cp.async.cg.shared.global [%0], [%1], 16;" :: "r"(dst), "l"(src));
}
__device__ __forceinline__ void cp_commit() {
    asm volatile("cp.async.commit_group;" ::: "memory");
}
template <int N>
__device__ __forceinline__ void cp_wait() {
    asm volatile("cp.async.wait_group %0;" :: "n"(N) : "memory");
}
__device__ __forceinline__ void ldm4(uint32_t& r0, uint32_t& r1, uint32_t& r2, uint32_t& r3, uint32_t a) {
    asm volatile("ldmatrix.sync.aligned.m8n8.x4.shared.b16 {%0,%1,%2,%3}, [%4];"
        : "=r"(r0), "=r"(r1), "=r"(r2), "=r"(r3) : "r"(a));
}
// S: f16 accumulators (2 regs)
#define MMA_F16H(d, a, bfr)                                                          \
    asm volatile("mma.sync.aligned.m16n8k16.row.col.f16.f16.f16.f16 "                \
        "{%0,%1},{%2,%3,%4,%5},{%6,%7},{%0,%1};"                                     \
        : "+r"((d)[0]), "+r"((d)[1])                                                 \
        : "r"((a)[0]), "r"((a)[1]), "r"((a)[2]), "r"((a)[3]), "r"((bfr)[0]), "r"((bfr)[1]))
// T: f32 accumulators (4 regs)
#define MMA_F16(d, a, bfr)                                                           \
    asm volatile("mma.sync.aligned.m16n8k16.row.col.f32.f16.f16.f32 "                \
        "{%0,%1,%2,%3},{%4,%5,%6,%7},{%8,%9},{%0,%1,%2,%3};"                         \
        : "+f"((d)[0]), "+f"((d)[1]), "+f"((d)[2]), "+f"((d)[3])                     \
        : "r"((a)[0]), "r"((a)[1]), "r"((a)[2]), "r"((a)[3]), "r"((bfr)[0]), "r"((bfr)[1]))

// ---------------- vectorized prep: float4 in -> 2x half2 out ----------------
constexpr size_t UF_ELEMS = (size_t)YP * Dn;          // 4,587,520
constexpr size_t X_ELEMS  = (size_t)Bn * LP * Dn;     // 10,485,760
constexpr size_t UF4 = UF_ELEMS / 4;
constexpr size_t X4  = X_ELEMS / 4;

__device__ __forceinline__ uint2 cvt4(float4 v) {
    __half2 lo = __float22half2_rn(make_float2(v.x, v.y));
    __half2 hi = __float22half2_rn(make_float2(v.z, v.w));
    uint2 r;
    r.x = *reinterpret_cast<uint32_t*>(&lo);
    r.y = *reinterpret_cast<uint32_t*>(&hi);
    return r;
}

__global__ __launch_bounds__(256) void prep_all(const float* __restrict__ U,
                                                const float* __restrict__ F,
                                                const float* __restrict__ x) {
    const size_t stride = (size_t)gridDim.x * blockDim.x;
    for (size_t i4 = (size_t)blockIdx.x * blockDim.x + threadIdx.x;
         i4 < UF4 + X4; i4 += stride) {
        if (i4 < UF4) {
            const size_t idx = i4 * 4;
            const int y = (int)(idx >> 9);
            float4 u = make_float4(0.f, 0.f, 0.f, 0.f), f = u;
            if (y < Yn) {
                u = *reinterpret_cast<const float4*>(U + idx);
                f = *reinterpret_cast<const float4*>(F + idx);
                const float s = 1.4426950408889634f;
                u.x *= s; u.y *= s; u.z *= s; u.w *= s;
            }
            *reinterpret_cast<uint2*>(g_U + idx) = cvt4(u);
            *reinterpret_cast<uint2*>(g_F + idx) = cvt4(f);
        } else {
            const size_t xi = (i4 - UF4) * 4;
            const size_t bl = xi >> 9;
            const int l = (int)(bl % LP);
            const int b = (int)(bl / LP);
            const int d = (int)(xi & 511);
            float4 v = make_float4(0.f, 0.f, 0.f, 0.f);
            if (l < Ln)
                v = *reinterpret_cast<const float4*>(x + ((size_t)b * Ln + l) * Dn + d);
            *reinterpret_cast<uint2*>(g_X + xi) = cvt4(v);
        }
    }
}

// ---------------- main fused kernel: 128 threads, 4 warps ----------------
__global__ __launch_bounds__(128, 2)
void attn_main(const float* __restrict__ fb, float* __restrict__ out) {
    extern __shared__ __align__(128) char smem[];
    uint32_t sbase;
    asm("{ .reg .u64 t; cvta.to.shared.u64 t, %1; cvt.u32.u64 %0, t; }" : "=r"(sbase) : "l"(smem));
    float2* red = (float2*)(smem + NST * STAGE);   // [2 wn][64 rows] = 1KB

    const int tid = threadIdx.x;
    const int wid = tid >> 5, lane = tid & 31;
    const int wm = wid >> 1, wn = wid & 1;        // warp grid 2(M) x 2(N); warp tile 32x64
    const int yt = blockIdx.x, b = blockIdx.y;

    // ---- loader mapping: 8 threads per 128B row; 16 rows per pass ----
    const int lr0 = tid >> 3;                     // 0..15
    const int lcc = tid & 7;                      // 16B chunk in 128B row

    auto issue = [&](int gi) {
        const int ci = gi & 7, lti = gi >> 3;
        const uint32_t sb = sbase + (uint32_t)(gi % NST) * STAGE;
        #pragma unroll
        for (int rr = 0; rr < 4; rr++) {
            const int row = lr0 + rr * 16;
            const uint32_t d = (uint32_t)row * 128 + (uint32_t)(slot_sw(row, lcc) << 4);
            const size_t s = ((size_t)(yt * TM + row)) * Dn + (size_t)ci * KC + lcc * 8;
            cpa16(sb + OFF_U + d, g_U + s);
            cpa16(sb + OFF_F + d, g_F + s);
        }
        #pragma unroll
        for (int rr = 0; rr < 8; rr++) {
            const int row = lr0 + rr * 16;
            const uint32_t d = (uint32_t)row * 128 + (uint32_t)(slot_sw(row, lcc) << 4);
            const size_t s = ((size_t)b * LP + (size_t)lti * TN + row) * Dn + (size_t)ci * KC + lcc * 8;
            cpa16(sb + OFF_X + d, g_X + s);
        }
    };

    // ---- ldmatrix per-thread invariants ----
    const int lg = lane >> 3, lr = lane & 7;
    const int rA0 = wm * 32 + lr + (lg & 1) * 8;
    const int cA = lg >> 1;
    const int rB0 = wn * 64 + lr + (lg >> 1) * 8;
    const int cB = lg & 1;
    uint32_t offA0[2], offB0[4];
    #pragma unroll
    for (int t2 = 0; t2 < 2; t2++) {
        const int ra = rA0 + t2 * 16;
        offA0[t2] = (uint32_t)ra * 128 + (uint32_t)(slot_sw(ra, cA) << 4);
    }
    #pragma unroll
    for (int bt = 0; bt < 4; bt++) {
        const int rb = rB0 + bt * 16;
        offB0[bt] = (uint32_t)rb * 128 + (uint32_t)(slot_sw(rb, cB) << 4);
    }

    const int quad = lane >> 2, tc = lane & 3;

    float z[4] = {0.f, 0.f, 0.f, 0.f}, nw[4] = {0.f, 0.f, 0.f, 0.f};

    issue(0); cp_commit();
    issue(1); cp_commit();

    for (int lt = 0; lt < NLT; lt++) {
        __half2 accS[2][8][2];                    // f16x2 accumulators for S
        float accT[2][8][4];
        #pragma unroll
        for (int mt = 0; mt < 2; mt++)
            #pragma unroll
            for (int nt = 0; nt < 8; nt++) {
                accS[mt][nt][0] = __half2half2(__ushort_as_half(0));
                accS[mt][nt][1] = __half2half2(__ushort_as_half(0));
                #pragma unroll
                for (int j = 0; j < 4; j++) accT[mt][nt][j] = 0.f;
            }

        for (int c = 0; c < NKC; c++) {
            const int g = lt * NKC + c;
            cp_wait<1>();
            __syncthreads();
            const uint32_t sb = sbase + (uint32_t)(g % NST) * STAGE;

            // hoist kk=0 fragment loads ahead of the cp.async burst: tensor
            // pipe starts while the LSU drains the prefetch for stage g+2
            uint32_t X[8][2], A0[2][4], A1[2][4];
            #pragma unroll
            for (int bt = 0; bt < 4; bt++)
                ldm4(X[bt*2][0], X[bt*2][1], X[bt*2+1][0], X[bt*2+1][1],
                     sb + OFF_X + offB0[bt]);
            #pragma unroll
            for (int mt = 0; mt < 2; mt++) {
                ldm4(A0[mt][0], A0[mt][1], A0[mt][2], A0[mt][3], sb + OFF_U + offA0[mt]);
                ldm4(A1[mt][0], A1[mt][1], A1[mt][2], A1[mt][3], sb + OFF_F + offA0[mt]);
            }

            const int gi = g + 2;
            if (gi < NG) issue(gi);
            cp_commit();

            #pragma unroll
            for (int kk = 0; kk < 4; kk++) {
                if (kk > 0) {
                    const uint32_t kx = (uint32_t)(kk << 5);
                    #pragma unroll
                    for (int bt = 0; bt < 4; bt++)
                        ldm4(X[bt*2][0], X[bt*2][1], X[bt*2+1][0], X[bt*2+1][1],
                             sb + OFF_X + (offB0[bt] ^ kx));
                    #pragma unroll
                    for (int mt = 0; mt < 2; mt++) {
                        ldm4(A0[mt][0], A0[mt][1], A0[mt][2], A0[mt][3], sb + OFF_U + (offA0[mt] ^ kx));
                        ldm4(A1[mt][0], A1[mt][1], A1[mt][2], A1[mt][3], sb + OFF_F + (offA0[mt] ^ kx));
                    }
                }
                #pragma unroll
                for (int mt = 0; mt < 2; mt++)
                    #pragma unroll
                    for (int nt = 0; nt < 8; nt++) {
                        uint32_t* sAcc = reinterpret_cast<uint32_t*>(accS[mt][nt]);
                        MMA_F16H(sAcc, A0[mt], X[nt]);
                        MMA_F16(accT[mt][nt], A1[mt], X[nt]);
                    }
            }
        }

        // softmax partial update: h2exp2 on packed scores, masked f32 accumulate
        #pragma unroll
        for (int nt = 0; nt < 8; nt++) {
            const int l0 = lt * TN + wn * 64 + nt * 8 + tc * 2;  // even; pair (l0, l0+1)
            const bool v = (l0 < Ln);                            // Ln even -> pair-uniform
            #pragma unroll
            for (int mt = 0; mt < 2; mt++)
                #pragma unroll
                for (int h = 0; h < 2; h++) {                    // row quad / quad+8
                    const __half2 e2 = h2exp2(accS[mt][nt][h]);
                    const float eA = __low2float(e2);
                    const float eB = __high2float(e2);
                    if (v) {
                        const int zi = mt * 2 + h;
                        z[zi] += eA + eB;
                        nw[zi] = fmaf(eA, accT[mt][nt][h * 2],     nw[zi]);
                        nw[zi] = fmaf(eB, accT[mt][nt][h * 2 + 1], nw[zi]);
                    }
                }
        }
    }

    // ---- final reduction ----
    cp_wait<0>();
    __syncthreads();
    #pragma unroll
    for (int zi = 0; zi < 4; zi++) {
        z[zi]  += __shfl_xor_sync(0xffffffffu, z[zi], 1);
        z[zi]  += __shfl_xor_sync(0xffffffffu, z[zi], 2);
        nw[zi] += __shfl_xor_sync(0xffffffffu, nw[zi], 1);
        nw[zi] += __shfl_xor_sync(0xffffffffu, nw[zi], 2);
    }
    if (tc == 0) {
        #pragma unroll
        for (int zi = 0; zi < 4; zi++) {
            const int mt = zi >> 1, rh = zi & 1;
            const int row = wm * 32 + mt * 16 + rh * 8 + quad;
            red[wn * 64 + row] = make_float2(z[zi], nw[zi]);
        }
    }
    __syncthreads();
    if (tid < 64) {
        float zz = 0.f, nn = 0.f;
        #pragma unroll
        for (int w = 0; w < 2; w++) { float2 v = red[w * 64 + tid]; zz += v.x; nn += v.y; }
        const int y = yt * TM + tid;
        if (y < Yn) out[(size_t)b * Yn + y] = nn / zz + fb[y];
    }
}

// ---------------- host launch ----------------
extern "C" void kernel_launch(void* const* d_in, const int* in_sizes, int n_in,
                              void* d_out, int out_size) {
    const float* x  = (const float*)d_in[0];
    const float* Uw = (const float*)d_in[1];
    const float* Fw = (const float*)d_in[2];
    const float* fb = (const float*)d_in[3];
    float* out = (float*)d_out;
    (void)in_sizes; (void)n_in; (void)out_size;

    prep_all<<<2048, 256>>>(Uw, Fw, x);

    const int dyn = NST * STAGE + 1024;
    cudaFuncSetAttribute(attn_main, cudaFuncAttributeMaxDynamicSharedMemorySize, dyn);
    attn_main<<<dim3(YT, Bn), 128, dyn>>>(fb, out);
}